// round 11
// baseline (speedup 1.0000x reference)
#include <cuda_runtime.h>
#include <cuda_fp16.h>
#include <cstdint>
#include <math.h>

#define B_  4
#define S_  2048
#define D_  1024
#define H_  16
#define DH_ 64

// ---------------------------------------------------------------------------
// Scratch (__device__ globals) — all mma operands stored as fp16
// ---------------------------------------------------------------------------
__device__ __half g_X  [B_*S_*D_];         // fp16 x
__device__ __half g_Q  [B_*H_*S_*DH_];     // [B,H,S,DH] (pre-scaled by 0.125*log2e)
__device__ __half g_K  [B_*H_*S_*DH_];     // [B,H,S,DH]
__device__ __half g_V  [B_*H_*S_*DH_];     // [B,H,S,DH]
__device__ __half g_C  [B_*S_*D_];         // [B,S,D] concat ctx
__device__ __half g_Wt [48*DH_*D_];        // row n=z*64+e over [1024]
__device__ __half g_WoT[D_*D_];            // [n][k] = Wo[k][n]

// ---------------------------------------------------------------------------
// Helpers
// ---------------------------------------------------------------------------
__device__ __forceinline__ uint32_t smem_u32(const void* p) {
    uint32_t a;
    asm("{ .reg .u64 t; cvta.to.shared.u64 t, %1; cvt.u32.u64 %0, t; }" : "=r"(a) : "l"(p));
    return a;
}
__device__ __forceinline__ void cp16(uint32_t sa, const void* g) {
    asm volatile("cp.async.cg.shared.global [%0], [%1], 16;" :: "r"(sa), "l"(g));
}
#define CP_COMMIT() asm volatile("cp.async.commit_group;" ::: "memory")
#define CP_WAIT(n)  asm volatile("cp.async.wait_group %0;" :: "n"(n) : "memory")

__device__ __forceinline__ float ex2(float x) {
    float y;
    asm("ex2.approx.f32 %0, %1;" : "=f"(y) : "f"(x));
    return y;
}

// D(16x8,f32) += A(16x16,f16) * B(16x8,f16)
__device__ __forceinline__ void mma16(float* c, uint32_t a0, uint32_t a1, uint32_t a2,
                                      uint32_t a3, uint32_t b0, uint32_t b1) {
    asm volatile(
        "mma.sync.aligned.m16n8k16.row.col.f32.f16.f16.f32 "
        "{%0,%1,%2,%3}, {%4,%5,%6,%7}, {%8,%9}, {%0,%1,%2,%3};"
        : "+f"(c[0]), "+f"(c[1]), "+f"(c[2]), "+f"(c[3])
        : "r"(a0), "r"(a1), "r"(a2), "r"(a3), "r"(b0), "r"(b1));
}
__device__ __forceinline__ void ldmat4(uint32_t& r0, uint32_t& r1, uint32_t& r2,
                                       uint32_t& r3, uint32_t addr) {
    asm volatile("ldmatrix.sync.aligned.m8n8.x4.shared.b16 {%0,%1,%2,%3}, [%4];"
                 : "=r"(r0), "=r"(r1), "=r"(r2), "=r"(r3) : "r"(addr));
}
__device__ __forceinline__ void ldmat4t(uint32_t& r0, uint32_t& r1, uint32_t& r2,
                                        uint32_t& r3, uint32_t addr) {
    asm volatile("ldmatrix.sync.aligned.m8n8.x4.trans.shared.b16 {%0,%1,%2,%3}, [%4];"
                 : "=r"(r0), "=r"(r1), "=r"(r2), "=r"(r3) : "r"(addr));
}
__device__ __forceinline__ uint32_t packh2(float lo, float hi) {
    __half2 h = __floats2half2_rn(lo, hi);
    return *(uint32_t*)&h;
}

// ---------------------------------------------------------------------------
// Fused prep kernel
// ---------------------------------------------------------------------------
__global__ __launch_bounds__(256) void prep_kernel(
    const float* __restrict__ x,
    const float* __restrict__ Wq, const float* __restrict__ Wk,
    const float* __restrict__ Wv, const float* __restrict__ Wo)
{
    __shared__ float t[32][33];
    const int bx = blockIdx.x;
    if (bx < 8192) {
        int i = (bx * 256 + threadIdx.x) * 4;
        float4 v = *(const float4*)&x[i];
        __half2 h0 = __floats2half2_rn(v.x, v.y);
        __half2 h1 = __floats2half2_rn(v.z, v.w);
        *(uint2*)&g_X[i] = make_uint2(*(uint32_t*)&h0, *(uint32_t*)&h1);
        return;
    }
    int tx = threadIdx.x & 31, ty = threadIdx.x >> 5;
    if (bx < 8192 + 3072) {
        int r = bx - 8192;
        int d0 = (r & 31) * 32;
        int e0 = ((r >> 5) & 1) * 32;
        int z  = r >> 6;
        int h = z / 3, mtx = z % 3;
        const float* W = (mtx == 0 ? Wq : (mtx == 1 ? Wk : Wv)) + h * D_ * DH_;
        __half* out = g_Wt + (size_t)z * DH_ * D_;
        #pragma unroll
        for (int i = 0; i < 4; i++)
            t[ty + 8 * i][tx] = W[(d0 + ty + 8 * i) * DH_ + e0 + tx];
        __syncthreads();
        #pragma unroll
        for (int i = 0; i < 4; i++)
            out[(e0 + ty + 8 * i) * D_ + d0 + tx] = __float2half_rn(t[tx][ty + 8 * i]);
    } else {
        int r = bx - 11264;
        int d0 = (r & 31) * 32;
        int n0 = (r >> 5) * 32;
        #pragma unroll
        for (int i = 0; i < 4; i++)
            t[ty + 8 * i][tx] = Wo[(d0 + ty + 8 * i) * D_ + n0 + tx];
        __syncthreads();
        #pragma unroll
        for (int i = 0; i < 4; i++)
            g_WoT[(n0 + ty + 8 * i) * D_ + d0 + tx] = __float2half_rn(t[tx][ty + 8 * i]);
    }
}

// ---------------------------------------------------------------------------
// 128x128x1024 fp16 GEMM, 4 warps of 64x64, BK=64, 3-stage cp.async.
// 128 threads. smem/stage: A[128][72] + B[128][72] halves = 36864 B.
// 3 stages = 110592 B; 2 CTAs/SM.
// ---------------------------------------------------------------------------
#define TSH 72
#define ABUF_B (128*TSH*2)      // 18432 bytes
#define STGB (2*ABUF_B)         // 36864 bytes
#define GEMM_SMEM (3*STGB)      // 110592 bytes

__device__ __forceinline__ void gemm_stage(const __half* __restrict__ Ag,
                                           const __half* __restrict__ Bg,
                                           uint32_t base, int k0, int buf, int tid)
{
    uint32_t ab = base + buf * STGB;
    uint32_t bb = ab + ABUF_B;
    #pragma unroll
    for (int t = 0; t < 8; t++) {
        int idx = tid + t * 128;
        int r = idx >> 3, c = (idx & 7) * 8;
        cp16(ab + (r * TSH + c) * 2, Ag + (size_t)r * D_ + k0 + c);
        cp16(bb + (r * TSH + c) * 2, Bg + (size_t)r * D_ + k0 + c);
    }
}

__device__ __forceinline__ void gemm_mainloop(const __half* __restrict__ Ag,
                                              const __half* __restrict__ Bg,
                                              float c[4][8][4], char* smc)
{
    const int tid = threadIdx.x;
    const int wid = tid >> 5, lane = tid & 31;
    const int wm = wid >> 1, wn = wid & 1;
    uint32_t base = smem_u32(smc);

    const int lrow_a = (lane & 7) + ((lane >> 3) & 1) * 8;
    const int acol   = (lane >> 4) * 8;
    const int lrow_b = (lane & 7) + ((lane >> 4) & 1) * 8;
    const int bcol   = ((lane >> 3) & 1) * 8;

    #pragma unroll
    for (int i = 0; i < 4; i++)
        #pragma unroll
        for (int j = 0; j < 8; j++)
            #pragma unroll
            for (int q = 0; q < 4; q++) c[i][j][q] = 0.f;

    gemm_stage(Ag, Bg, base, 0, 0, tid);
    CP_COMMIT();
    gemm_stage(Ag, Bg, base, 64, 1, tid);
    CP_COMMIT();

    for (int s = 0; s < 16; s++) {
        if (s < 15) { CP_WAIT(1); } else { CP_WAIT(0); }
        __syncthreads();
        if (s + 2 < 16) {
            gemm_stage(Ag, Bg, base, (s + 2) * 64, (s + 2) % 3, tid);
            CP_COMMIT();
        }

        uint32_t Abase = base + (s % 3) * STGB;
        uint32_t Bbase = Abase + ABUF_B;
        #pragma unroll
        for (int ks = 0; ks < 4; ks++) {
            uint32_t a[4][4], b[8][2];
            #pragma unroll
            for (int sub = 0; sub < 4; sub++) {
                int row = wm * 64 + sub * 16 + lrow_a;
                ldmat4(a[sub][0], a[sub][1], a[sub][2], a[sub][3],
                       Abase + (row * TSH + ks * 16 + acol) * 2);
            }
            #pragma unroll
            for (int p = 0; p < 4; p++) {
                int row = wn * 64 + p * 16 + lrow_b;
                ldmat4(b[2*p][0], b[2*p][1], b[2*p+1][0], b[2*p+1][1],
                       Bbase + (row * TSH + ks * 16 + bcol) * 2);
            }
            #pragma unroll
            for (int sub = 0; sub < 4; sub++)
                #pragma unroll
                for (int nt = 0; nt < 8; nt++)
                    mma16(c[sub][nt], a[sub][0], a[sub][1], a[sub][2], a[sub][3],
                          b[nt][0], b[nt][1]);
        }
    }
}

// ---------------------------------------------------------------------------
// QKV GEMM: grid (64, 24), 128 threads. Each warp's 64-col span = one z.
// ---------------------------------------------------------------------------
#define QSCALE 0.1803368801111137f   // 0.125 * log2(e)

__global__ __launch_bounds__(128, 2) void qkv_gemm_kernel(
    const float* __restrict__ bq, const float* __restrict__ bk,
    const float* __restrict__ bv)
{
    extern __shared__ char smc[];
    const int mt = blockIdx.x, bn = blockIdx.y;
    float c[4][8][4];
    gemm_mainloop(g_X + (size_t)mt * 128 * D_,
                  g_Wt + (size_t)bn * 128 * D_, c, smc);

    const int tid = threadIdx.x;
    const int wid = tid >> 5, lane = tid & 31;
    const int g = lane >> 2, tg = lane & 3;
    const int wm = wid >> 1, wn = wid & 1;

    const int z = bn * 2 + wn;
    const int h = z / 3, mtx = z % 3;
    const float* bias = (mtx == 0 ? bq : (mtx == 1 ? bk : bv)) + h * DH_;
    __half* dst = (mtx == 0 ? g_Q : (mtx == 1 ? g_K : g_V));
    const float scale = (mtx == 0) ? QSCALE : 1.0f;

    #pragma unroll
    for (int sub = 0; sub < 4; sub++) {
        #pragma unroll
        for (int half = 0; half < 2; half++) {
            int m = mt * 128 + wm * 64 + sub * 16 + g + half * 8;
            int bi = m >> 11, si = m & 2047;
            __half* row = dst + ((size_t)(bi * H_ + h) * S_ + si) * DH_;
            #pragma unroll
            for (int nt = 0; nt < 8; nt++) {
                int e = nt * 8 + 2 * tg;
                float v0 = (c[sub][nt][half * 2 + 0] + bias[e]) * scale;
                float v1 = (c[sub][nt][half * 2 + 1] + bias[e + 1]) * scale;
                *(__half2*)&row[e] = __floats2half2_rn(v0, v1);
            }
        }
    }
}

// ---------------------------------------------------------------------------
// Output projection GEMM: grid (64, 8), 128 threads. fp32 out.
// ---------------------------------------------------------------------------
__global__ __launch_bounds__(128, 2) void proj_gemm_kernel(
    const float* __restrict__ bo, float* __restrict__ out)
{
    extern __shared__ char smc[];
    const int mt = blockIdx.x, bn = blockIdx.y;
    float c[4][8][4];
    gemm_mainloop(g_C + (size_t)mt * 128 * D_,
                  g_WoT + (size_t)bn * 128 * D_, c, smc);

    const int tid = threadIdx.x;
    const int wid = tid >> 5, lane = tid & 31;
    const int g = lane >> 2, tg = lane & 3;
    const int wm = wid >> 1, wn = wid & 1;

    #pragma unroll
    for (int sub = 0; sub < 4; sub++) {
        #pragma unroll
        for (int half = 0; half < 2; half++) {
            int m = mt * 128 + wm * 64 + sub * 16 + g + half * 8;
            #pragma unroll
            for (int nt = 0; nt < 8; nt++) {
                int n = bn * 128 + wn * 64 + nt * 8 + 2 * tg;
                float v0 = c[sub][nt][half * 2 + 0] + bo[n];
                float v1 = c[sub][nt][half * 2 + 1] + bo[n + 1];
                *(float2*)&out[(size_t)m * D_ + n] = make_float2(v0, v1);
            }
        }
    }
}

// ---------------------------------------------------------------------------
// Flash attention: 128 threads, 4 warps of 32 q-rows (CTA = 128 q-rows).
// 128-key stages (2 kt-subtiles per stage), 3-stage pipeline, 2 CTAs/SM.
// fp16 mma + ldmatrix, register P, static-max exp2 softmax, ones-mma sums.
// ---------------------------------------------------------------------------
#define AKS 72
#define KBUF_B (128*AKS*2)       // 18432 (128 keys of K)
#define AT_STGB (2*KBUF_B)       // 36864 (K then V)
#define ATTN_SMEM (3*AT_STGB)    // 110592

__device__ __forceinline__ void attn_stage(const __half* __restrict__ Kg,
                                           const __half* __restrict__ Vg,
                                           uint32_t base, int st, int buf, int tid)
{
    const __half* ksrc = Kg + (size_t)st * 128 * DH_;
    const __half* vsrc = Vg + (size_t)st * 128 * DH_;
    uint32_t kb = base + buf * AT_STGB;
    uint32_t vb = kb + KBUF_B;
    #pragma unroll
    for (int t = 0; t < 8; t++) {
        int idx = tid + t * 128;
        int r = idx >> 3, c = (idx & 7) * 8;
        cp16(kb + (r * AKS + c) * 2, ksrc + r * DH_ + c);
        cp16(vb + (r * AKS + c) * 2, vsrc + r * DH_ + c);
    }
}

__global__ __launch_bounds__(128, 2) void attn_kernel()
{
    extern __shared__ char smc[];
    const int tid = threadIdx.x;
    const int wid = tid >> 5, lane = tid & 31;
    const int g = lane >> 2, tg = lane & 3;
    const int qt = blockIdx.x, h = blockIdx.y, b = blockIdx.z;
    const int bh = b * H_ + h;
    uint32_t base = smem_u32(smc);

    const int lrow_b = (lane & 7) + ((lane >> 4) & 1) * 8;   // K (non-trans)
    const int bcol   = ((lane >> 3) & 1) * 8;
    const int lrow_v = (lane & 7) + ((lane >> 3) & 1) * 8;   // V (trans)
    const int vcol   = ((lane >> 4) & 1) * 8;

    // Q fragments: warp owns rows wid*32 .. wid*32+31 (2 sub-tiles of 16)
    const __half* Qg = g_Q + ((size_t)bh * S_ + qt * 128 + wid * 32) * DH_;
    uint32_t qf[2][4][4];
    #pragma unroll
    for (int sub = 0; sub < 2; sub++) {
        #pragma unroll
        for (int ks = 0; ks < 4; ks++) {
            int col = ks * 16 + 2 * tg;
            int r = sub * 16 + g;
            qf[sub][ks][0] = *(const uint32_t*)&Qg[r * DH_ + col];
            qf[sub][ks][1] = *(const uint32_t*)&Qg[(r + 8) * DH_ + col];
            qf[sub][ks][2] = *(const uint32_t*)&Qg[r * DH_ + col + 8];
            qf[sub][ks][3] = *(const uint32_t*)&Qg[(r + 8) * DH_ + col + 8];
        }
    }

    float oc[2][8][4];
    #pragma unroll
    for (int sub = 0; sub < 2; sub++)
        #pragma unroll
        for (int nt = 0; nt < 8; nt++)
            #pragma unroll
            for (int q = 0; q < 4; q++) oc[sub][nt][q] = 0.f;
    float lsum[2][2] = {{0.f, 0.f}, {0.f, 0.f}};

    const __half* Kg = g_K + (size_t)bh * S_ * DH_;
    const __half* Vg = g_V + (size_t)bh * S_ * DH_;

    attn_stage(Kg, Vg, base, 0, 0, tid);
    CP_COMMIT();
    attn_stage(Kg, Vg, base, 1, 1, tid);
    CP_COMMIT();

    for (int st = 0; st < 16; st++) {
        if (st < 15) { CP_WAIT(1); } else { CP_WAIT(0); }
        __syncthreads();
        if (st + 2 < 16) {
            attn_stage(Kg, Vg, base, st + 2, (st + 2) % 3, tid);
            CP_COMMIT();
        }

        uint32_t Sbase = base + (st % 3) * AT_STGB;

        #pragma unroll
        for (int half = 0; half < 2; half++) {
            uint32_t Kbase = Sbase + half * 64 * AKS * 2;
            uint32_t Vbase = Sbase + KBUF_B + half * 64 * AKS * 2;

            // S' = Q @ K^T (log2 domain)
            float sc[2][8][4];
            #pragma unroll
            for (int sub = 0; sub < 2; sub++)
                #pragma unroll
                for (int nt = 0; nt < 8; nt++)
                    #pragma unroll
                    for (int q = 0; q < 4; q++) sc[sub][nt][q] = 0.f;

            #pragma unroll
            for (int ks = 0; ks < 4; ks++) {
                uint32_t kb[8][2];
                #pragma unroll
                for (int p = 0; p < 4; p++) {
                    int row = p * 16 + lrow_b;
                    ldmat4(kb[2*p][0], kb[2*p][1], kb[2*p+1][0], kb[2*p+1][1],
                           Kbase + (row * AKS + ks * 16 + bcol) * 2);
                }
                #pragma unroll
                for (int sub = 0; sub < 2; sub++)
                    #pragma unroll
                    for (int nt = 0; nt < 8; nt++)
                        mma16(sc[sub][nt], qf[sub][ks][0], qf[sub][ks][1],
                              qf[sub][ks][2], qf[sub][ks][3], kb[nt][0], kb[nt][1]);
            }

            // p = 2^s, pack into A-fragments
            uint32_t pf[2][4][4];
            #pragma unroll
            for (int sub = 0; sub < 2; sub++)
                #pragma unroll
                for (int j = 0; j < 4; j++) {
                    pf[sub][j][0] = packh2(ex2(sc[sub][2*j][0]),   ex2(sc[sub][2*j][1]));
                    pf[sub][j][1] = packh2(ex2(sc[sub][2*j][2]),   ex2(sc[sub][2*j][3]));
                    pf[sub][j][2] = packh2(ex2(sc[sub][2*j+1][0]), ex2(sc[sub][2*j+1][1]));
                    pf[sub][j][3] = packh2(ex2(sc[sub][2*j+1][2]), ex2(sc[sub][2*j+1][3]));
                }

            // Row sums via ones-mma
            const uint32_t ones = 0x3C003C00u;
            #pragma unroll
            for (int sub = 0; sub < 2; sub++) {
                float ls[4] = {0.f, 0.f, 0.f, 0.f};
                #pragma unroll
                for (int j = 0; j < 4; j++)
                    mma16(ls, pf[sub][j][0], pf[sub][j][1], pf[sub][j][2], pf[sub][j][3],
                          ones, ones);
                lsum[sub][0] += ls[0];
                lsum[sub][1] += ls[2];
            }

            // O += P @ V
            #pragma unroll
            for (int j = 0; j < 4; j++) {
                uint32_t vb[8][2];
                #pragma unroll
                for (int p = 0; p < 4; p++) {
                    int row = j * 16 + lrow_v;
                    ldmat4t(vb[2*p][0], vb[2*p][1], vb[2*p+1][0], vb[2*p+1][1],
                            Vbase + (row * AKS + p * 16 + vcol) * 2);
                }
                #pragma unroll
                for (int sub = 0; sub < 2; sub++)
                    #pragma unroll
                    for (int nt = 0; nt < 8; nt++)
                        mma16(oc[sub][nt], pf[sub][j][0], pf[sub][j][1],
                              pf[sub][j][2], pf[sub][j][3], vb[nt][0], vb[nt][1]);
            }
        }
    }

    // epilogue: normalize, store ctx (fp16) in concat layout
    #pragma unroll
    for (int sub = 0; sub < 2; sub++) {
        float inv0 = 1.f / lsum[sub][0], inv1 = 1.f / lsum[sub][1];
        int s0 = qt * 128 + wid * 32 + sub * 16 + g;
        __half* row0 = g_C + ((size_t)b * S_ + s0) * D_ + h * DH_;
        __half* row1 = row0 + 8 * D_;
        #pragma unroll
        for (int nt = 0; nt < 8; nt++) {
            int cidx = nt * 8 + 2 * tg;
            *(__half2*)&row0[cidx] =
                __floats2half2_rn(oc[sub][nt][0] * inv0, oc[sub][nt][1] * inv0);
            *(__half2*)&row1[cidx] =
                __floats2half2_rn(oc[sub][nt][2] * inv1, oc[sub][nt][3] * inv1);
        }
    }
}

// ---------------------------------------------------------------------------
extern "C" void kernel_launch(void* const* d_in, const int* in_sizes, int n_in,
                              void* d_out, int out_size)
{
    const float* x  = (const float*)d_in[0];
    const float* Wq = (const float*)d_in[1];
    const float* bq = (const float*)d_in[2];
    const float* Wk = (const float*)d_in[3];
    const float* bk = (const float*)d_in[4];
    const float* Wv = (const float*)d_in[5];
    const float* bv = (const float*)d_in[6];
    const float* Wo = (const float*)d_in[7];
    const float* bo = (const float*)d_in[8];
    float* out = (float*)d_out;

    cudaFuncSetAttribute(attn_kernel,
                         cudaFuncAttributeMaxDynamicSharedMemorySize, ATTN_SMEM);
    cudaFuncSetAttribute(qkv_gemm_kernel,
                         cudaFuncAttributeMaxDynamicSharedMemorySize, GEMM_SMEM);
    cudaFuncSetAttribute(proj_gemm_kernel,
                         cudaFuncAttributeMaxDynamicSharedMemorySize, GEMM_SMEM);

    prep_kernel<<<12288, 256>>>(x, Wq, Wk, Wv, Wo);
    qkv_gemm_kernel<<<dim3(64, 24), 128, GEMM_SMEM>>>(bq, bk, bv);
    attn_kernel<<<dim3(16, 16, 4), 128, ATTN_SMEM>>>();
    proj_gemm_kernel<<<dim3(64, 8), 128, GEMM_SMEM>>>(bo, out);
}

// round 12
// speedup vs baseline: 1.0542x; 1.0542x over previous
#include <cuda_runtime.h>
#include <cuda_fp16.h>
#include <cstdint>
#include <math.h>

#define B_  4
#define S_  2048
#define D_  1024
#define H_  16
#define DH_ 64

// ---------------------------------------------------------------------------
// Scratch (__device__ globals) — all mma operands stored as fp16
// ---------------------------------------------------------------------------
__device__ __half g_X  [B_*S_*D_];         // fp16 x
__device__ __half g_Q  [B_*H_*S_*DH_];     // [B,H,S,DH] (pre-scaled by 0.125*log2e)
__device__ __half g_K  [B_*H_*S_*DH_];     // [B,H,S,DH]
__device__ __half g_V  [B_*H_*S_*DH_];     // [B,H,S,DH]
__device__ __half g_C  [B_*S_*D_];         // [B,S,D] concat ctx
__device__ __half g_Wt [48*DH_*D_];        // row n=z*64+e over [1024]
__device__ __half g_WoT[D_*D_];            // [n][k] = Wo[k][n]

// dependency counters (zeroed by prep_kernel each launch)
__device__ int g_cnt_qkv[B_];              // -> 384 each (qkv CTAs per batch)
__device__ int g_cnt_attn[B_*16];          // per (b,qt) -> 16 (one per head)

// ---------------------------------------------------------------------------
// Helpers
// ---------------------------------------------------------------------------
__device__ __forceinline__ uint32_t smem_u32(const void* p) {
    uint32_t a;
    asm("{ .reg .u64 t; cvta.to.shared.u64 t, %1; cvt.u32.u64 %0, t; }" : "=r"(a) : "l"(p));
    return a;
}
__device__ __forceinline__ void cp16(uint32_t sa, const void* g) {
    asm volatile("cp.async.cg.shared.global [%0], [%1], 16;" :: "r"(sa), "l"(g));
}
#define CP_COMMIT() asm volatile("cp.async.commit_group;" ::: "memory")
#define CP_WAIT(n)  asm volatile("cp.async.wait_group %0;" :: "n"(n) : "memory")

__device__ __forceinline__ float ex2(float x) {
    float y;
    asm("ex2.approx.f32 %0, %1;" : "=f"(y) : "f"(x));
    return y;
}

// D(16x8,f32) += A(16x16,f16) * B(16x8,f16)
__device__ __forceinline__ void mma16(float* c, uint32_t a0, uint32_t a1, uint32_t a2,
                                      uint32_t a3, uint32_t b0, uint32_t b1) {
    asm volatile(
        "mma.sync.aligned.m16n8k16.row.col.f32.f16.f16.f32 "
        "{%0,%1,%2,%3}, {%4,%5,%6,%7}, {%8,%9}, {%0,%1,%2,%3};"
        : "+f"(c[0]), "+f"(c[1]), "+f"(c[2]), "+f"(c[3])
        : "r"(a0), "r"(a1), "r"(a2), "r"(a3), "r"(b0), "r"(b1));
}
__device__ __forceinline__ void ldmat4(uint32_t& r0, uint32_t& r1, uint32_t& r2,
                                       uint32_t& r3, uint32_t addr) {
    asm volatile("ldmatrix.sync.aligned.m8n8.x4.shared.b16 {%0,%1,%2,%3}, [%4];"
                 : "=r"(r0), "=r"(r1), "=r"(r2), "=r"(r3) : "r"(addr));
}
__device__ __forceinline__ void ldmat4t(uint32_t& r0, uint32_t& r1, uint32_t& r2,
                                        uint32_t& r3, uint32_t addr) {
    asm volatile("ldmatrix.sync.aligned.m8n8.x4.trans.shared.b16 {%0,%1,%2,%3}, [%4];"
                 : "=r"(r0), "=r"(r1), "=r"(r2), "=r"(r3) : "r"(addr));
}
__device__ __forceinline__ uint32_t packh2(float lo, float hi) {
    __half2 h = __floats2half2_rn(lo, hi);
    return *(uint32_t*)&h;
}

// ---------------------------------------------------------------------------
// Fused prep kernel (also zeroes dependency counters for this launch)
// ---------------------------------------------------------------------------
__global__ __launch_bounds__(256) void prep_kernel(
    const float* __restrict__ x,
    const float* __restrict__ Wq, const float* __restrict__ Wk,
    const float* __restrict__ Wv, const float* __restrict__ Wo)
{
    __shared__ float t[32][33];
    const int bx = blockIdx.x;
    if (bx == 0) {
        int tid = threadIdx.x;
        if (tid < B_) g_cnt_qkv[tid] = 0;
        else if (tid < B_ + B_ * 16) g_cnt_attn[tid - B_] = 0;
    }
    if (bx < 8192) {
        int i = (bx * 256 + threadIdx.x) * 4;
        float4 v = *(const float4*)&x[i];
        __half2 h0 = __floats2half2_rn(v.x, v.y);
        __half2 h1 = __floats2half2_rn(v.z, v.w);
        *(uint2*)&g_X[i] = make_uint2(*(uint32_t*)&h0, *(uint32_t*)&h1);
        return;
    }
    int tx = threadIdx.x & 31, ty = threadIdx.x >> 5;
    if (bx < 8192 + 3072) {
        int r = bx - 8192;
        int d0 = (r & 31) * 32;
        int e0 = ((r >> 5) & 1) * 32;
        int z  = r >> 6;
        int h = z / 3, mtx = z % 3;
        const float* W = (mtx == 0 ? Wq : (mtx == 1 ? Wk : Wv)) + h * D_ * DH_;
        __half* out = g_Wt + (size_t)z * DH_ * D_;
        #pragma unroll
        for (int i = 0; i < 4; i++)
            t[ty + 8 * i][tx] = W[(d0 + ty + 8 * i) * DH_ + e0 + tx];
        __syncthreads();
        #pragma unroll
        for (int i = 0; i < 4; i++)
            out[(e0 + ty + 8 * i) * D_ + d0 + tx] = __float2half_rn(t[tx][ty + 8 * i]);
    } else {
        int r = bx - 11264;
        int d0 = (r & 31) * 32;
        int n0 = (r >> 5) * 32;
        #pragma unroll
        for (int i = 0; i < 4; i++)
            t[ty + 8 * i][tx] = Wo[(d0 + ty + 8 * i) * D_ + n0 + tx];
        __syncthreads();
        #pragma unroll
        for (int i = 0; i < 4; i++)
            g_WoT[(n0 + ty + 8 * i) * D_ + d0 + tx] = __float2half_rn(t[tx][ty + 8 * i]);
    }
}

// ---------------------------------------------------------------------------
// GEMM mainloop: 128x128x1024, 4 warps of 64x64, BK=64, 3-stage cp.async.
// smem/stage: A[128][72] + B[128][72] halves = 36864 B; 3 stages = 110592 B.
// ---------------------------------------------------------------------------
#define TSH 72
#define ABUF_B (128*TSH*2)      // 18432 bytes
#define STGB (2*ABUF_B)         // 36864 bytes
#define FUSED_SMEM (3*STGB)     // 110592 bytes (GEMM and attn use same size)

__device__ __forceinline__ void gemm_stage(const __half* __restrict__ Ag,
                                           const __half* __restrict__ Bg,
                                           uint32_t base, int k0, int buf, int tid)
{
    uint32_t ab = base + buf * STGB;
    uint32_t bb = ab + ABUF_B;
    #pragma unroll
    for (int t = 0; t < 8; t++) {
        int idx = tid + t * 128;
        int r = idx >> 3, c = (idx & 7) * 8;
        cp16(ab + (r * TSH + c) * 2, Ag + (size_t)r * D_ + k0 + c);
        cp16(bb + (r * TSH + c) * 2, Bg + (size_t)r * D_ + k0 + c);
    }
}

__device__ __forceinline__ void gemm_mainloop(const __half* __restrict__ Ag,
                                              const __half* __restrict__ Bg,
                                              float c[4][8][4], char* smc)
{
    const int tid = threadIdx.x;
    const int wid = tid >> 5, lane = tid & 31;
    const int wm = wid >> 1, wn = wid & 1;
    uint32_t base = smem_u32(smc);

    const int lrow_a = (lane & 7) + ((lane >> 3) & 1) * 8;
    const int acol   = (lane >> 4) * 8;
    const int lrow_b = (lane & 7) + ((lane >> 4) & 1) * 8;
    const int bcol   = ((lane >> 3) & 1) * 8;

    #pragma unroll
    for (int i = 0; i < 4; i++)
        #pragma unroll
        for (int j = 0; j < 8; j++)
            #pragma unroll
            for (int q = 0; q < 4; q++) c[i][j][q] = 0.f;

    gemm_stage(Ag, Bg, base, 0, 0, tid);
    CP_COMMIT();
    gemm_stage(Ag, Bg, base, 64, 1, tid);
    CP_COMMIT();

    for (int s = 0; s < 16; s++) {
        if (s < 15) { CP_WAIT(1); } else { CP_WAIT(0); }
        __syncthreads();
        if (s + 2 < 16) {
            gemm_stage(Ag, Bg, base, (s + 2) * 64, (s + 2) % 3, tid);
            CP_COMMIT();
        }

        uint32_t Abase = base + (s % 3) * STGB;
        uint32_t Bbase = Abase + ABUF_B;
        #pragma unroll
        for (int ks = 0; ks < 4; ks++) {
            uint32_t a[4][4], b[8][2];
            #pragma unroll
            for (int sub = 0; sub < 4; sub++) {
                int row = wm * 64 + sub * 16 + lrow_a;
                ldmat4(a[sub][0], a[sub][1], a[sub][2], a[sub][3],
                       Abase + (row * TSH + ks * 16 + acol) * 2);
            }
            #pragma unroll
            for (int p = 0; p < 4; p++) {
                int row = wn * 64 + p * 16 + lrow_b;
                ldmat4(b[2*p][0], b[2*p][1], b[2*p+1][0], b[2*p+1][1],
                       Bbase + (row * TSH + ks * 16 + bcol) * 2);
            }
            #pragma unroll
            for (int sub = 0; sub < 4; sub++)
                #pragma unroll
                for (int nt = 0; nt < 8; nt++)
                    mma16(c[sub][nt], a[sub][0], a[sub][1], a[sub][2], a[sub][3],
                          b[nt][0], b[nt][1]);
        }
    }
}

#define QSCALE 0.1803368801111137f   // 0.125 * log2(e)

// ---------------------------------------------------------------------------
// Phase bodies
// ---------------------------------------------------------------------------
__device__ void qkv_body(int u, const float* __restrict__ bq,
                         const float* __restrict__ bk,
                         const float* __restrict__ bv, char* smc)
{
    // u = ((b*16 + mtb)*24 + bn)   (batch-major so attn deps clear early)
    const int bn = u % 24;
    const int mtq = u / 24;          // b*16 + mtb
    const int b = mtq >> 4;
    const int mt = mtq;              // global m-tile (= b*16 + mtb)

    float c[4][8][4];
    gemm_mainloop(g_X + (size_t)mt * 128 * D_,
                  g_Wt + (size_t)bn * 128 * D_, c, smc);

    const int tid = threadIdx.x;
    const int wid = tid >> 5, lane = tid & 31;
    const int g = lane >> 2, tg = lane & 3;
    const int wm = wid >> 1, wn = wid & 1;

    const int z = bn * 2 + wn;
    const int h = z / 3, mtx = z % 3;
    const float* bias = (mtx == 0 ? bq : (mtx == 1 ? bk : bv)) + h * DH_;
    __half* dst = (mtx == 0 ? g_Q : (mtx == 1 ? g_K : g_V));
    const float scale = (mtx == 0) ? QSCALE : 1.0f;

    #pragma unroll
    for (int sub = 0; sub < 4; sub++) {
        #pragma unroll
        for (int half = 0; half < 2; half++) {
            int m = mt * 128 + wm * 64 + sub * 16 + g + half * 8;
            int bi = m >> 11, si = m & 2047;
            __half* row = dst + ((size_t)(bi * H_ + h) * S_ + si) * DH_;
            #pragma unroll
            for (int nt = 0; nt < 8; nt++) {
                int e = nt * 8 + 2 * tg;
                float v0 = (c[sub][nt][half * 2 + 0] + bias[e]) * scale;
                float v1 = (c[sub][nt][half * 2 + 1] + bias[e + 1]) * scale;
                *(__half2*)&row[e] = __floats2half2_rn(v0, v1);
            }
        }
    }

    __syncthreads();
    if (tid == 0) {
        __threadfence();
        atomicAdd(&g_cnt_qkv[b], 1);
    }
}

#define AKS 72
#define KBUF_B (128*AKS*2)       // 18432 (128 keys of K)
#define AT_STGB (2*KBUF_B)       // 36864 (K then V)

__device__ __forceinline__ void attn_stage(const __half* __restrict__ Kg,
                                           const __half* __restrict__ Vg,
                                           uint32_t base, int st, int buf, int tid)
{
    const __half* ksrc = Kg + (size_t)st * 128 * DH_;
    const __half* vsrc = Vg + (size_t)st * 128 * DH_;
    uint32_t kb = base + buf * AT_STGB;
    uint32_t vb = kb + KBUF_B;
    #pragma unroll
    for (int t = 0; t < 8; t++) {
        int idx = tid + t * 128;
        int r = idx >> 3, c = (idx & 7) * 8;
        cp16(kb + (r * AKS + c) * 2, ksrc + r * DH_ + c);
        cp16(vb + (r * AKS + c) * 2, vsrc + r * DH_ + c);
    }
}

__device__ void attn_body(int a, char* smc)
{
    // a = (b*16 + qt)*16 + h
    const int h = a & 15;
    const int bq16 = a >> 4;         // b*16 + qt
    const int b = bq16 >> 4;
    const int qt = bq16 & 15;

    const int tid = threadIdx.x;
    const int wid = tid >> 5, lane = tid & 31;
    const int g = lane >> 2, tg = lane & 3;
    const int bh = b * H_ + h;
    uint32_t base = smem_u32(smc);

    // wait for this batch's QKV to be complete
    if (tid == 0) {
        while (((volatile int*)g_cnt_qkv)[b] < 384) __nanosleep(100);
    }
    __syncthreads();
    __threadfence();

    const int lrow_b = (lane & 7) + ((lane >> 4) & 1) * 8;   // K (non-trans)
    const int bcol   = ((lane >> 3) & 1) * 8;
    const int lrow_v = (lane & 7) + ((lane >> 3) & 1) * 8;   // V (trans)
    const int vcol   = ((lane >> 4) & 1) * 8;

    const __half* Qg = g_Q + ((size_t)bh * S_ + qt * 128 + wid * 32) * DH_;
    uint32_t qf[2][4][4];
    #pragma unroll
    for (int sub = 0; sub < 2; sub++) {
        #pragma unroll
        for (int ks = 0; ks < 4; ks++) {
            int col = ks * 16 + 2 * tg;
            int r = sub * 16 + g;
            qf[sub][ks][0] = *(const uint32_t*)&Qg[r * DH_ + col];
            qf[sub][ks][1] = *(const uint32_t*)&Qg[(r + 8) * DH_ + col];
            qf[sub][ks][2] = *(const uint32_t*)&Qg[r * DH_ + col + 8];
            qf[sub][ks][3] = *(const uint32_t*)&Qg[(r + 8) * DH_ + col + 8];
        }
    }

    float oc[2][8][4];
    #pragma unroll
    for (int sub = 0; sub < 2; sub++)
        #pragma unroll
        for (int nt = 0; nt < 8; nt++)
            #pragma unroll
            for (int q = 0; q < 4; q++) oc[sub][nt][q] = 0.f;
    float lsum[2][2] = {{0.f, 0.f}, {0.f, 0.f}};

    const __half* Kg = g_K + (size_t)bh * S_ * DH_;
    const __half* Vg = g_V + (size_t)bh * S_ * DH_;

    attn_stage(Kg, Vg, base, 0, 0, tid);
    CP_COMMIT();
    attn_stage(Kg, Vg, base, 1, 1, tid);
    CP_COMMIT();

    for (int st = 0; st < 16; st++) {
        if (st < 15) { CP_WAIT(1); } else { CP_WAIT(0); }
        __syncthreads();
        if (st + 2 < 16) {
            attn_stage(Kg, Vg, base, st + 2, (st + 2) % 3, tid);
            CP_COMMIT();
        }

        uint32_t Sbase = base + (st % 3) * AT_STGB;

        #pragma unroll
        for (int half = 0; half < 2; half++) {
            uint32_t Kbase = Sbase + half * 64 * AKS * 2;
            uint32_t Vbase = Sbase + KBUF_B + half * 64 * AKS * 2;

            float sc[2][8][4];
            #pragma unroll
            for (int sub = 0; sub < 2; sub++)
                #pragma unroll
                for (int nt = 0; nt < 8; nt++)
                    #pragma unroll
                    for (int q = 0; q < 4; q++) sc[sub][nt][q] = 0.f;

            #pragma unroll
            for (int ks = 0; ks < 4; ks++) {
                uint32_t kb[8][2];
                #pragma unroll
                for (int p = 0; p < 4; p++) {
                    int row = p * 16 + lrow_b;
                    ldmat4(kb[2*p][0], kb[2*p][1], kb[2*p+1][0], kb[2*p+1][1],
                           Kbase + (row * AKS + ks * 16 + bcol) * 2);
                }
                #pragma unroll
                for (int sub = 0; sub < 2; sub++)
                    #pragma unroll
                    for (int nt = 0; nt < 8; nt++)
                        mma16(sc[sub][nt], qf[sub][ks][0], qf[sub][ks][1],
                              qf[sub][ks][2], qf[sub][ks][3], kb[nt][0], kb[nt][1]);
            }

            uint32_t pf[2][4][4];
            #pragma unroll
            for (int sub = 0; sub < 2; sub++)
                #pragma unroll
                for (int j = 0; j < 4; j++) {
                    pf[sub][j][0] = packh2(ex2(sc[sub][2*j][0]),   ex2(sc[sub][2*j][1]));
                    pf[sub][j][1] = packh2(ex2(sc[sub][2*j][2]),   ex2(sc[sub][2*j][3]));
                    pf[sub][j][2] = packh2(ex2(sc[sub][2*j+1][0]), ex2(sc[sub][2*j+1][1]));
                    pf[sub][j][3] = packh2(ex2(sc[sub][2*j+1][2]), ex2(sc[sub][2*j+1][3]));
                }

            const uint32_t ones = 0x3C003C00u;
            #pragma unroll
            for (int sub = 0; sub < 2; sub++) {
                float ls[4] = {0.f, 0.f, 0.f, 0.f};
                #pragma unroll
                for (int j = 0; j < 4; j++)
                    mma16(ls, pf[sub][j][0], pf[sub][j][1], pf[sub][j][2], pf[sub][j][3],
                          ones, ones);
                lsum[sub][0] += ls[0];
                lsum[sub][1] += ls[2];
            }

            #pragma unroll
            for (int j = 0; j < 4; j++) {
                uint32_t vb[8][2];
                #pragma unroll
                for (int p = 0; p < 4; p++) {
                    int row = j * 16 + lrow_v;
                    ldmat4t(vb[2*p][0], vb[2*p][1], vb[2*p+1][0], vb[2*p+1][1],
                            Vbase + (row * AKS + p * 16 + vcol) * 2);
                }
                #pragma unroll
                for (int sub = 0; sub < 2; sub++)
                    #pragma unroll
                    for (int nt = 0; nt < 8; nt++)
                        mma16(oc[sub][nt], pf[sub][j][0], pf[sub][j][1],
                              pf[sub][j][2], pf[sub][j][3], vb[nt][0], vb[nt][1]);
            }
        }
    }

    #pragma unroll
    for (int sub = 0; sub < 2; sub++) {
        float inv0 = 1.f / lsum[sub][0], inv1 = 1.f / lsum[sub][1];
        int s0 = qt * 128 + wid * 32 + sub * 16 + g;
        __half* row0 = g_C + ((size_t)b * S_ + s0) * D_ + h * DH_;
        __half* row1 = row0 + 8 * D_;
        #pragma unroll
        for (int nt = 0; nt < 8; nt++) {
            int cidx = nt * 8 + 2 * tg;
            *(__half2*)&row0[cidx] =
                __floats2half2_rn(oc[sub][nt][0] * inv0, oc[sub][nt][1] * inv0);
            *(__half2*)&row1[cidx] =
                __floats2half2_rn(oc[sub][nt][2] * inv1, oc[sub][nt][3] * inv1);
        }
    }

    __syncthreads();
    if (tid == 0) {
        __threadfence();
        atomicAdd(&g_cnt_attn[bq16], 1);
    }
}

__device__ void proj_body(int p, const float* __restrict__ bo,
                          float* __restrict__ out, char* smc)
{
    // p = mt*8 + bn   (mt = b*16 + qt)
    const int mt = p >> 3, bn = p & 7;
    const int tid = threadIdx.x;

    // wait for all 16 heads of this (b,qt) tile
    if (tid == 0) {
        while (((volatile int*)g_cnt_attn)[mt] < 16) __nanosleep(100);
    }
    __syncthreads();
    __threadfence();

    float c[4][8][4];
    gemm_mainloop(g_C + (size_t)mt * 128 * D_,
                  g_WoT + (size_t)bn * 128 * D_, c, smc);

    const int wid = tid >> 5, lane = tid & 31;
    const int g = lane >> 2, tg = lane & 3;
    const int wm = wid >> 1, wn = wid & 1;

    #pragma unroll
    for (int sub = 0; sub < 4; sub++) {
        #pragma unroll
        for (int half = 0; half < 2; half++) {
            int m = mt * 128 + wm * 64 + sub * 16 + g + half * 8;
            #pragma unroll
            for (int nt = 0; nt < 8; nt++) {
                int n = bn * 128 + wn * 64 + nt * 8 + 2 * tg;
                float v0 = c[sub][nt][half * 2 + 0] + bo[n];
                float v1 = c[sub][nt][half * 2 + 1] + bo[n + 1];
                *(float2*)&out[(size_t)m * D_ + n] = make_float2(v0, v1);
            }
        }
    }
}

// ---------------------------------------------------------------------------
// Fused kernel: bids [0,1536) qkv, [1536,2560) attn, [2560,3072) proj
// ---------------------------------------------------------------------------
__global__ __launch_bounds__(128, 2) void fused_kernel(
    const float* __restrict__ bq, const float* __restrict__ bk,
    const float* __restrict__ bv, const float* __restrict__ bo,
    float* __restrict__ out)
{
    extern __shared__ char smc[];
    const int bid = blockIdx.x;
    if (bid < 1536) {
        qkv_body(bid, bq, bk, bv, smc);
    } else if (bid < 2560) {
        attn_body(bid - 1536, smc);
    } else {
        proj_body(bid - 2560, bo, out, smc);
    }
}

// ---------------------------------------------------------------------------
extern "C" void kernel_launch(void* const* d_in, const int* in_sizes, int n_in,
                              void* d_out, int out_size)
{
    const float* x  = (const float*)d_in[0];
    const float* Wq = (const float*)d_in[1];
    const float* bq = (const float*)d_in[2];
    const float* Wk = (const float*)d_in[3];
    const float* bk = (const float*)d_in[4];
    const float* Wv = (const float*)d_in[5];
    const float* bv = (const float*)d_in[6];
    const float* Wo = (const float*)d_in[7];
    const float* bo = (const float*)d_in[8];
    float* out = (float*)d_out;

    cudaFuncSetAttribute(fused_kernel,
                         cudaFuncAttributeMaxDynamicSharedMemorySize, FUSED_SMEM);

    prep_kernel<<<12288, 256>>>(x, Wq, Wk, Wv, Wo);
    fused_kernel<<<3072, 128, FUSED_SMEM>>>(bq, bk, bv, bo, out);
}